// round 10
// baseline (speedup 1.0000x reference)
#include <cuda_runtime.h>

#define SDIM    7
#define NCELL   49
#define BATCH   16384
#define DSTRIDE 30
#define NPAIR   (BATCH * NCELL)          // 802816
#define NCLASS  20

#define TILE        256                  // pairs per tile
#define NTILES      (NPAIR / TILE)       // 3136 (exact)
#define K1_BLOCKS   147                  // 3*49: tile stride 147*256 ≡ 0 mod 49
#define K1_THREADS  256
#define NWARPS      (K1_THREADS / 32)    // 8
#define TOTWARPS    (K1_BLOCKS * NWARPS) // 1176
#define STAGES      3
#define TILE_WORDS  (TILE * DSTRIDE)     // 7680 floats per tensor per tile
#define STAGE_WORDS (2 * TILE_WORDS)     // 15360 (out + tgt)
#define SMEM_BYTES  (STAGES * STAGE_WORDS * 4)   // 184320 B -> 1 block/SM, all 147 resident
#define CHUNKS_PER_TENSOR (TILE_WORDS * 4 / 16)  // 1920 x 16B

__device__ float    g_has[NPAIR];          // 3.2 MB (stays L2-resident for epilogue)
__device__ float    g_cellsums[3 * NCELL]; // XW | CM | CLS (zero-init; reset each run)
__device__ float    g_coef[NCELL + 1];     // A[0..48], Ktot at [49]
__device__ unsigned g_ticket;              // zero-init; reset each run
__device__ unsigned g_ticket2;             // zero-init; reset each run
__device__ unsigned g_flag;                // zero-init; coef-ready flag, reset each run

__device__ __forceinline__ float decode_dim(const void* p) {
    if (p == nullptr) return 448.0f;
    int v = *(const int*)p;
    if (v > 0 && v < (1 << 24)) return (float)v;
    float f = __int_as_float(v);
    if (f > 0.0f && f < 16777216.0f) return f;
    double d = *(const double*)p;
    return (float)d;
}

__device__ __forceinline__ void cp_async16(unsigned saddr, const void* gptr) {
    asm volatile("cp.async.cg.shared.global [%0], [%1], 16;" :: "r"(saddr), "l"(gptr));
}
__device__ __forceinline__ void cp_commit() {
    asm volatile("cp.async.commit_group;");
}
template <int N> __device__ __forceinline__ void cp_wait() {
    asm volatile("cp.async.wait_group %0;" :: "n"(N));
}

__device__ __forceinline__ void load_tile(float* stage, int tile,
                                          const char* obase0, const char* tbase0,
                                          int tid) {
    const char* obase = obase0 + (size_t)tile * (TILE * DSTRIDE * 4);
    const char* tbase = tbase0 + (size_t)tile * (TILE * DSTRIDE * 4);
    unsigned so = (unsigned)__cvta_generic_to_shared(stage);
    unsigned st = (unsigned)__cvta_generic_to_shared(stage + TILE_WORDS);
    #pragma unroll
    for (int k = 0; k < 15; k++) {                 // 3840 chunks / 256 threads
        int c = k * K1_THREADS + tid;
        if (c < CHUNKS_PER_TENSOR)
            cp_async16(so + c * 16, obase + (size_t)c * 16);
        else {
            int c2 = c - CHUNKS_PER_TENSOR;
            cp_async16(st + c2 * 16, tbase + (size_t)c2 * 16);
        }
    }
}

// Warp-level row epilogue: loss[b] = sum_c has[b,c]*A[c] + Ktot
__device__ __forceinline__ float row_dot(const float* __restrict__ hp,
                                         int lane, float A1, float A2) {
    float v = __ldg(hp + lane) * A1;
    if (lane < NCELL - 32)
        v += __ldg(hp + lane + 32) * A2;
    #pragma unroll
    for (int s = 16; s > 0; s >>= 1)
        v += __shfl_xor_sync(0xFFFFFFFFu, v, s);
    return v;
}

__global__ void __launch_bounds__(K1_THREADS)
yolo_main_kernel(const float* __restrict__ outp,
                 const float* __restrict__ tgtp,
                 const void* wp, const void* hp_dim,
                 float* __restrict__ loss)
{
    extern __shared__ float smem[];
    __shared__ float sc[3 * NCELL];
    __shared__ float s_rd[3 * NCELL];
    __shared__ unsigned s_rank;

    const float W = decode_dim(wp);
    const float H = decode_dim(hp_dim);
    const float cw = W * (1.0f / SDIM);
    const float ch = H * (1.0f / SDIM);

    const int tid = threadIdx.x;
    const int cell = (blockIdx.x * K1_THREADS + tid) % NCELL;   // loop-invariant
    const float jx = (float)(cell % SDIM);
    const float iy = (float)(cell / SDIM);

    const char* ob = (const char*)outp;
    const char* tb = (const char*)tgtp;

    #pragma unroll
    for (int s = 0; s < STAGES; s++) {
        load_tile(smem + s * STAGE_WORDS, blockIdx.x + s * K1_BLOCKS, ob, tb, tid);
        cp_commit();
    }

    float a_xw = 0.0f, a_cm = 0.0f, a_cls = 0.0f;
    int stage = 0;

    for (int j = blockIdx.x; j < NTILES; j += K1_BLOCKS) {
        cp_wait<STAGES - 1>();
        __syncthreads();

        const float2* o2 = (const float2*)(smem + stage * STAGE_WORDS + tid * DSTRIDE);
        const float2* t2 = (const float2*)(smem + stage * STAGE_WORDS + TILE_WORDS + tid * DSTRIDE);

        float o[DSTRIDE], t[DSTRIDE];
        #pragma unroll
        for (int k = 0; k < DSTRIDE / 2; k++) {
            float2 vo = o2[k];
            float2 vt = t2[k];
            o[2 * k] = vo.x; o[2 * k + 1] = vo.y;
            t[2 * k] = vt.x; t[2 * k + 1] = vt.y;
        }

        const float tx = t[0], ty = t[1];
        const float tw = t[2] * W, th = t[3] * H;
        const float has = t[4];
        const float tcx = (jx + tx) * cw, tcy = (iy + ty) * ch;
        const float tx0 = tcx - 0.5f * tw, tx1 = tcx + 0.5f * tw;
        const float ty0 = tcy - 0.5f * th, ty1 = tcy + 0.5f * th;
        const float t_area = (tx1 - tx0) * (ty1 - ty0);

        float iou[2];
        #pragma unroll
        for (int p = 0; p < 2; p++) {
            const float px = o[5 * p], py = o[5 * p + 1];
            const float pw = o[5 * p + 3] * W, ph = o[5 * p + 4] * H;
            const float pcx = (jx + px) * cw, pcy = (iy + py) * ch;
            const float px0 = pcx - 0.5f * pw, px1 = pcx + 0.5f * pw;
            const float py0 = pcy - 0.5f * ph, py1 = pcy + 0.5f * ph;
            const float iw = fmaxf(fminf(px1, tx1) - fmaxf(px0, tx0), 0.0f);
            const float ih = fmaxf(fminf(py1, ty1) - fmaxf(py0, ty0), 0.0f);
            const float inter = iw * ih;
            const float p_area = (px1 - px0) * (py1 - py0);
            iou[p] = inter / (p_area + t_area - inter + 1e-9f);
        }
        const float bc = (iou[1] >= iou[0]) ? o[9] : o[4];   // last-index tie-break

        const float dx = tx - o[5];
        const float dy = ty - o[6];
        const float dw = sqrtf(tw) - sqrtf(o[8] * W);
        const float dh = sqrtf(th) - sqrtf(o[9] * H);
        const float dc = has - o[9];

        a_xw += dx * dx + dy * dy + dw * dw + dh * dh;
        a_cm += dc * dc;

        float ec = 0.0f;
        #pragma unroll
        for (int c = 0; c < NCLASS; c++) {
            const float d = t[10 + c] - o[10 + c] * bc;
            ec += d * d;
        }
        a_cls += ec;

        g_has[(size_t)j * TILE + tid] = has;   // coalesced STG (stays in L2)

        __syncthreads();

        int jn = j + STAGES * K1_BLOCKS;
        if (jn < NTILES)
            load_tile(smem + stage * STAGE_WORDS, jn, ob, tb, tid);
        cp_commit();

        stage = (stage == STAGES - 1) ? 0 : stage + 1;
    }

    // ---- block reduction keyed on actual cell (32 < 49 -> conflict-free) ----
    if (tid < 3 * NCELL) sc[tid] = 0.0f;
    __syncthreads();
    atomicAdd(&sc[cell],             a_xw);
    atomicAdd(&sc[NCELL + cell],     a_cm);
    atomicAdd(&sc[2 * NCELL + cell], a_cls);
    __syncthreads();
    if (tid < 3 * NCELL)
        atomicAdd(&g_cellsums[tid], sc[tid]);

    // ---- ticket: last block publishes coefficients + releases flag ----
    __threadfence();
    if (tid == 0) s_rank = atomicAdd(&g_ticket, 1u);
    __syncthreads();
    if (s_rank == K1_BLOCKS - 1) {
        __threadfence();                       // all 147 contributions visible
        if (tid < 3 * NCELL) s_rd[tid] = g_cellsums[tid];
        __syncthreads();
        if (tid < NCELL) {
            const float xw  = s_rd[tid];
            const float cm  = s_rd[NCELL + tid];
            const float cls = s_rd[2 * NCELL + tid];
            g_coef[tid] = 5.0f * xw + 0.5f * cm;           // A[c]
            s_rd[tid]   = 0.5f * cm + cls;                 // K[c] (reuse smem)
        }
        __syncthreads();
        if (tid == 0) {
            float kt = 0.0f;
            #pragma unroll
            for (int c = 0; c < NCELL; c++) kt += s_rd[c];
            g_coef[NCELL] = kt;                            // Ktot
        }
        if (tid < 3 * NCELL) g_cellsums[tid] = 0.0f;       // reset for replay
        if (tid == 0) {
            g_ticket = 0u;
            __threadfence();                               // coef+resets before flag
            asm volatile("st.release.gpu.u32 [%0], %1;" :: "l"(&g_flag), "r"(1u));
        }
    }

    // ---- grid-wide wait (all 147 blocks co-resident: 1 block/SM) ----
    if (tid == 0 && s_rank != K1_BLOCKS - 1) {
        unsigned f;
        do {
            asm volatile("ld.acquire.gpu.u32 %0, [%1];" : "=r"(f) : "l"(&g_flag));
        } while (f == 0);
    }
    __syncthreads();
    __threadfence_block();

    // ---- in-kernel epilogue: warp-per-row from L2-hot g_has ----
    {
        const int lane = tid & 31;
        const int gw   = blockIdx.x * NWARPS + (tid >> 5);    // 0..1175
        const float A1 = __ldg(g_coef + lane);
        const float A2 = (lane < NCELL - 32) ? __ldg(g_coef + lane + 32) : 0.0f;
        const float Kt = __ldg(g_coef + NCELL);

        int b = gw;
        // 2-way unroll: two independent load+shfl chains in flight
        while (b + TOTWARPS < BATCH) {
            float v0 = row_dot(g_has + (size_t)b * NCELL,             lane, A1, A2);
            float v1 = row_dot(g_has + (size_t)(b + TOTWARPS) * NCELL, lane, A1, A2);
            if (lane == 0) {
                loss[b]            = v0 + Kt;
                loss[b + TOTWARPS] = v1 + Kt;
            }
            b += 2 * TOTWARPS;
        }
        while (b < BATCH) {
            float v0 = row_dot(g_has + (size_t)b * NCELL, lane, A1, A2);
            if (lane == 0) loss[b] = v0 + Kt;
            b += TOTWARPS;
        }
    }

    // ---- final cleanup ticket: last finisher resets flag for next replay ----
    __threadfence();
    __syncthreads();
    if (tid == 0) {
        unsigned r2 = atomicAdd(&g_ticket2, 1u);
        if (r2 == K1_BLOCKS - 1) {
            g_ticket2 = 0u;
            asm volatile("st.release.gpu.u32 [%0], %1;" :: "l"(&g_flag), "r"(0u));
        }
    }
}

extern "C" void kernel_launch(void* const* d_in, const int* in_sizes, int n_in,
                              void* d_out, int out_size)
{
    const float* o  = (const float*)d_in[0];
    const float* t  = (const float*)d_in[1];
    const void*  wp = (n_in > 2) ? d_in[2] : nullptr;
    const void*  hp = (n_in > 3) ? d_in[3] : nullptr;

    cudaFuncSetAttribute(yolo_main_kernel,
                         cudaFuncAttributeMaxDynamicSharedMemorySize, SMEM_BYTES);

    yolo_main_kernel<<<K1_BLOCKS, K1_THREADS, SMEM_BYTES>>>(o, t, wp, hp, (float*)d_out);
}

// round 13
// speedup vs baseline: 1.1050x; 1.1050x over previous
#include <cuda_runtime.h>

#define SDIM    7
#define NCELL   49
#define BATCH   16384
#define DSTRIDE 30
#define NPAIR   (BATCH * NCELL)          // 802816 = 2^14 * 49
#define NCLASS  20

#define TILE        448                  // 2^6*7 divides NPAIR: 1792 tiles exact
#define NTILES      (NPAIR / TILE)       // 1792
#define K1_BLOCKS   147                  // 147 ≡ 0 (mod 49) -> cell invariant for ANY TILE
#define K1_THREADS  448                  // 14 warps/SM (was 8)
#define STAGES      2
#define TILE_WORDS  (TILE * DSTRIDE)     // 13440 floats per tensor per tile
#define STAGE_WORDS (2 * TILE_WORDS)     // 26880 (out + tgt)
#define SMEM_BYTES  (STAGES * STAGE_WORDS * 4)   // 215040 B <= 227KB -> 1 block/SM
#define CHUNKS_PER_TENSOR (TILE_WORDS * 4 / 16)  // 3360 x 16B
#define CHUNK_ITERS ((2 * CHUNKS_PER_TENSOR) / K1_THREADS)  // 15

__device__ float    g_has[NPAIR];          // 3.2 MB (L2-hot for final kernel)
__device__ float    g_cellsums[3 * NCELL]; // XW | CM | CLS (zero-init, reset by last block)
__device__ float    g_coef[2 * NCELL];     // A | K
__device__ unsigned g_ticket;              // zero-init, reset by last block

__device__ __forceinline__ float decode_dim(const void* p) {
    if (p == nullptr) return 448.0f;
    int v = *(const int*)p;
    if (v > 0 && v < (1 << 24)) return (float)v;
    float f = __int_as_float(v);
    if (f > 0.0f && f < 16777216.0f) return f;
    double d = *(const double*)p;
    return (float)d;
}

__device__ __forceinline__ void cp_async16(unsigned saddr, const void* gptr) {
    asm volatile("cp.async.cg.shared.global [%0], [%1], 16;" :: "r"(saddr), "l"(gptr));
}
__device__ __forceinline__ void cp_commit() {
    asm volatile("cp.async.commit_group;");
}
template <int N> __device__ __forceinline__ void cp_wait() {
    asm volatile("cp.async.wait_group %0;" :: "n"(N));
}

__device__ __forceinline__ void load_tile(float* stage, int tile,
                                          const char* obase0, const char* tbase0,
                                          int tid) {
    const char* obase = obase0 + (size_t)tile * (TILE * DSTRIDE * 4);
    const char* tbase = tbase0 + (size_t)tile * (TILE * DSTRIDE * 4);
    unsigned so = (unsigned)__cvta_generic_to_shared(stage);
    unsigned st = (unsigned)__cvta_generic_to_shared(stage + TILE_WORDS);
    #pragma unroll
    for (int k = 0; k < CHUNK_ITERS; k++) {        // 6720 chunks / 448 threads
        int c = k * K1_THREADS + tid;
        if (c < CHUNKS_PER_TENSOR)
            cp_async16(so + c * 16, obase + (size_t)c * 16);
        else {
            int c2 = c - CHUNKS_PER_TENSOR;
            cp_async16(st + c2 * 16, tbase + (size_t)c2 * 16);
        }
    }
}

__global__ void __launch_bounds__(K1_THREADS)
yolo_main_kernel(const float* __restrict__ outp,
                 const float* __restrict__ tgtp,
                 const void* wp, const void* hp)
{
    extern __shared__ float smem[];
    __shared__ float sc[3 * NCELL];
    __shared__ float s_rd[3 * NCELL];
    __shared__ unsigned s_rank;

    const float W = decode_dim(wp);
    const float H = decode_dim(hp);
    const float cw = W * (1.0f / SDIM);
    const float ch = H * (1.0f / SDIM);

    const int tid = threadIdx.x;
    // pair index = tile*TILE + tid; tile advances by 147 ≡ 0 (mod 49)
    const int cell = (blockIdx.x * TILE + tid) % NCELL;   // loop-invariant
    const float jx = (float)(cell % SDIM);
    const float iy = (float)(cell / SDIM);

    const char* ob = (const char*)outp;
    const char* tb = (const char*)tgtp;

    // prologue (every block has >= 12 tiles >= STAGES)
    #pragma unroll
    for (int s = 0; s < STAGES; s++) {
        load_tile(smem + s * STAGE_WORDS, blockIdx.x + s * K1_BLOCKS, ob, tb, tid);
        cp_commit();
    }

    float a_xw = 0.0f, a_cm = 0.0f, a_cls = 0.0f;
    int stage = 0;

    for (int j = blockIdx.x; j < NTILES; j += K1_BLOCKS) {
        cp_wait<STAGES - 1>();
        __syncthreads();

        const float2* o2 = (const float2*)(smem + stage * STAGE_WORDS + tid * DSTRIDE);
        const float2* t2 = (const float2*)(smem + stage * STAGE_WORDS + TILE_WORDS + tid * DSTRIDE);

        float o[DSTRIDE], t[DSTRIDE];
        #pragma unroll
        for (int k = 0; k < DSTRIDE / 2; k++) {
            float2 vo = o2[k];
            float2 vt = t2[k];
            o[2 * k] = vo.x; o[2 * k + 1] = vo.y;
            t[2 * k] = vt.x; t[2 * k + 1] = vt.y;
        }

        const float tx = t[0], ty = t[1];
        const float tw = t[2] * W, th = t[3] * H;
        const float has = t[4];
        const float tcx = (jx + tx) * cw, tcy = (iy + ty) * ch;
        const float tx0 = tcx - 0.5f * tw, tx1 = tcx + 0.5f * tw;
        const float ty0 = tcy - 0.5f * th, ty1 = tcy + 0.5f * th;
        const float t_area = (tx1 - tx0) * (ty1 - ty0);

        float iou[2];
        #pragma unroll
        for (int p = 0; p < 2; p++) {
            const float px = o[5 * p], py = o[5 * p + 1];
            const float pw = o[5 * p + 3] * W, ph = o[5 * p + 4] * H;
            const float pcx = (jx + px) * cw, pcy = (iy + py) * ch;
            const float px0 = pcx - 0.5f * pw, px1 = pcx + 0.5f * pw;
            const float py0 = pcy - 0.5f * ph, py1 = pcy + 0.5f * ph;
            const float iw = fmaxf(fminf(px1, tx1) - fmaxf(px0, tx0), 0.0f);
            const float ih = fmaxf(fminf(py1, ty1) - fmaxf(py0, ty0), 0.0f);
            const float inter = iw * ih;
            const float p_area = (px1 - px0) * (py1 - py0);
            iou[p] = inter / (p_area + t_area - inter + 1e-9f);
        }
        const float bc = (iou[1] >= iou[0]) ? o[9] : o[4];   // last-index tie-break

        const float dx = tx - o[5];
        const float dy = ty - o[6];
        const float dw = sqrtf(tw) - sqrtf(o[8] * W);
        const float dh = sqrtf(th) - sqrtf(o[9] * H);
        const float dc = has - o[9];

        a_xw += dx * dx + dy * dy + dw * dw + dh * dh;
        a_cm += dc * dc;

        float ec = 0.0f;
        #pragma unroll
        for (int c = 0; c < NCLASS; c++) {
            const float d = t[10 + c] - o[10 + c] * bc;
            ec += d * d;
        }
        a_cls += ec;

        g_has[(size_t)j * TILE + tid] = has;   // coalesced STG

        __syncthreads();

        int jn = j + STAGES * K1_BLOCKS;
        if (jn < NTILES)
            load_tile(smem + stage * STAGE_WORDS, jn, ob, tb, tid);
        cp_commit();

        stage ^= 1;
    }

    // block reduction keyed on actual cell (32 < 49 -> conflict-free atomics)
    if (tid < 3 * NCELL) sc[tid] = 0.0f;
    __syncthreads();
    atomicAdd(&sc[cell],             a_xw);
    atomicAdd(&sc[NCELL + cell],     a_cm);
    atomicAdd(&sc[2 * NCELL + cell], a_cls);
    __syncthreads();
    if (tid < 3 * NCELL)
        atomicAdd(&g_cellsums[tid], sc[tid]);

    // last block computes coefficients and resets state for replay
    __threadfence();
    if (tid == 0) s_rank = atomicAdd(&g_ticket, 1u);
    __syncthreads();
    if (s_rank == K1_BLOCKS - 1) {
        __threadfence();
        if (tid < 3 * NCELL) s_rd[tid] = g_cellsums[tid];
        __syncthreads();
        if (tid < NCELL) {
            const float xw  = s_rd[tid];
            const float cm  = s_rd[NCELL + tid];
            const float cls = s_rd[2 * NCELL + tid];
            g_coef[tid]         = 5.0f * xw + 0.5f * cm;   // A
            g_coef[NCELL + tid] = 0.5f * cm + cls;         // K
        }
        if (tid < 3 * NCELL) g_cellsums[tid] = 0.0f;
        if (tid == 0) g_ticket = 0u;
        __threadfence();
    }
}

// Warp handles 2 rows with independent load+SHFL chains (ILP over the
// ~400cyc serial chain that limited the 1-row/warp version to 5.6us).
__global__ void __launch_bounds__(256)
yolo_final_kernel(float* __restrict__ loss)
{
    const int lane = threadIdx.x & 31;
    const int gw = (blockIdx.x * 256 + threadIdx.x) >> 5;  // 0..8191
    const int b0 = gw * 2;

    const float A1 = __ldg(g_coef + lane);
    const float A2 = (lane < NCELL - 32) ? __ldg(g_coef + lane + 32) : 0.0f;
    const float K1 = __ldg(g_coef + NCELL + lane);
    const float K2 = (lane < NCELL - 32) ? __ldg(g_coef + NCELL + lane + 32) : 0.0f;

    const float* h0 = g_has + (size_t)b0 * NCELL;
    const float* h1 = h0 + NCELL;

    float v0 = __ldg(h0 + lane) * A1 + K1;
    float v1 = __ldg(h1 + lane) * A1 + K1;
    if (lane < NCELL - 32) {
        v0 += __ldg(h0 + lane + 32) * A2 + K2;
        v1 += __ldg(h1 + lane + 32) * A2 + K2;
    }

    #pragma unroll
    for (int s = 16; s > 0; s >>= 1) {
        v0 += __shfl_xor_sync(0xFFFFFFFFu, v0, s);
        v1 += __shfl_xor_sync(0xFFFFFFFFu, v1, s);
    }

    if (lane == 0) {
        loss[b0]     = v0;
        loss[b0 + 1] = v1;
    }
}

extern "C" void kernel_launch(void* const* d_in, const int* in_sizes, int n_in,
                              void* d_out, int out_size)
{
    const float* o  = (const float*)d_in[0];
    const float* t  = (const float*)d_in[1];
    const void*  wp = (n_in > 2) ? d_in[2] : nullptr;
    const void*  hp = (n_in > 3) ? d_in[3] : nullptr;

    cudaFuncSetAttribute(yolo_main_kernel,
                         cudaFuncAttributeMaxDynamicSharedMemorySize, SMEM_BYTES);

    yolo_main_kernel<<<K1_BLOCKS, K1_THREADS, SMEM_BYTES>>>(o, t, wp, hp);
    yolo_final_kernel<<<BATCH / 16, 256>>>((float*)d_out);   // 1024 blocks, 2 rows/warp
}